// round 15
// baseline (speedup 1.0000x reference)
#include <cuda_runtime.h>
#include <cuda_fp16.h>
#include <cstdint>
#include <math.h>

// Problem constants
#define R_ROWS  16384   // N*C
#define SPATIAL 1024    // H*W
#define MDIM    512     // mem_dim
#define HIDDIM  512     // spatial/2

// d_out section offsets (floats)
#define OFF_OUTPUT   ((size_t)0)
#define OFF_ATTSP    ((size_t)16777216)
#define OFF_INFLAT   ((size_t)33554432)
#define OFF_MEMNORM  ((size_t)50331648)
#define OFF_ATT      ((size_t)50855936)

// Device scratch (allocation-free)
__device__ float  g_h[MDIM * HIDDIM];
__device__ float  g_memproc[MDIM * SPATIAL];
__device__ float  g_invnorm[R_ROWS];
__device__ __half g_xh[(size_t)R_ROWS * SPATIAL];    // fp16 x (fallback path)
__device__ __half g_mnh[MDIM * SPATIAL];             // fp16 memory_norm
__device__ __half g_mnTh[SPATIAL * MDIM];            // fp16 memory_norm^T
__device__ __half g_atth[(size_t)R_ROWS * MDIM];     // fp16 logits/att (flagged blocks)
__device__ char   g_x8[(size_t)R_ROWS * SPATIAL];    // int8 x*invnorm (*127)
__device__ char   g_mn8[MDIM * SPATIAL];             // int8 memory_norm (*127)
__device__ float2 g_stats[(size_t)R_ROWS * 4];       // per-row per-tile (max, sumexp)
__device__ int    g_bflag[R_ROWS / 128];             // per-128-row survivor flags

// ============================================================================
// mma.sync helpers (sm_80+ — base compute_103 target safe)
// ============================================================================
__device__ __forceinline__ void mma8_tf32(float* c, uint32_t a0, uint32_t a1,
                                          uint32_t a2, uint32_t a3,
                                          uint32_t b0, uint32_t b1) {
    asm volatile(
        "mma.sync.aligned.m16n8k8.row.col.f32.tf32.tf32.f32 "
        "{%0,%1,%2,%3}, {%4,%5,%6,%7}, {%8,%9}, {%0,%1,%2,%3};"
        : "+f"(c[0]), "+f"(c[1]), "+f"(c[2]), "+f"(c[3])
        : "r"(a0), "r"(a1), "r"(a2), "r"(a3), "r"(b0), "r"(b1));
}

__device__ __forceinline__ void mma16_f16(float* c, uint32_t a0, uint32_t a1,
                                          uint32_t a2, uint32_t a3,
                                          uint32_t b0, uint32_t b1) {
    asm volatile(
        "mma.sync.aligned.m16n8k16.row.col.f32.f16.f16.f32 "
        "{%0,%1,%2,%3}, {%4,%5,%6,%7}, {%8,%9}, {%0,%1,%2,%3};"
        : "+f"(c[0]), "+f"(c[1]), "+f"(c[2]), "+f"(c[3])
        : "r"(a0), "r"(a1), "r"(a2), "r"(a3), "r"(b0), "r"(b1));
}

__device__ __forceinline__ void mma32_s8(int* c, uint32_t a0, uint32_t a1,
                                         uint32_t a2, uint32_t a3,
                                         uint32_t b0, uint32_t b1) {
    asm volatile(
        "mma.sync.aligned.m16n8k32.row.col.s32.s8.s8.s32 "
        "{%0,%1,%2,%3}, {%4,%5,%6,%7}, {%8,%9}, {%0,%1,%2,%3};"
        : "+r"(c[0]), "+r"(c[1]), "+r"(c[2]), "+r"(c[3])
        : "r"(a0), "r"(a1), "r"(a2), "r"(a3), "r"(b0), "r"(b1));
}

__device__ __forceinline__ void ldmx4(uint32_t& r0, uint32_t& r1,
                                      uint32_t& r2, uint32_t& r3, uint32_t addr) {
    asm volatile("ldmatrix.sync.aligned.m8n8.x4.shared.b16 {%0,%1,%2,%3}, [%4];"
                 : "=r"(r0), "=r"(r1), "=r"(r2), "=r"(r3) : "r"(addr));
}

__device__ __forceinline__ uint32_t tf32_hi(float x) {
    uint32_t h;
    asm("cvt.rna.tf32.f32 %0, %1;" : "=r"(h) : "f"(x));
    return h;
}

__device__ __forceinline__ void cp16(uint32_t dst, const void* src) {
    asm volatile("cp.async.cg.shared.global [%0], [%1], 16;" :: "r"(dst), "l"(src));
}

__device__ __forceinline__ uint32_t pack_half2(float a, float b) {
    __half2 h = __floats2half2_rn(a, b);
    return *reinterpret_cast<uint32_t*>(&h);
}

__device__ __forceinline__ char q8(float v) {
    return (char)__float2int_rn(127.0f * v);
}

__device__ __forceinline__ float warp_sum(float v) {
#pragma unroll
    for (int o = 16; o > 0; o >>= 1) v += __shfl_xor_sync(0xffffffffu, v, o);
    return v;
}
__device__ __forceinline__ float warp_max(float v) {
#pragma unroll
    for (int o = 16; o > 0; o >>= 1) v = fmaxf(v, __shfl_xor_sync(0xffffffffu, v, o));
    return v;
}

// ============================================================================
// tf32 NT GEMM tile (device fn) — precision-critical MLP path.
// ============================================================================
#define SSTRIDE 36
#define TILEF   (128 * SSTRIDE)
#define STAGEF  (2 * TILEF)
#define GEMM_SMEM_BYTES (3 * STAGEF * 4)

__device__ void mlp_tile(
    int Ntot, int K,
    const float* __restrict__ A, const float* __restrict__ B,
    float* __restrict__ C, const float* __restrict__ bias,
    int bm, int bn)
{
    extern __shared__ float smf[];
    const uint32_t sbase = (uint32_t)__cvta_generic_to_shared(smf);
    const int tid  = threadIdx.x;
    const int wid  = tid >> 5;
    const int lane = tid & 31;
    const int wm   = wid & 1;
    const int wn   = wid >> 1;
    const int tr   = lane >> 2;
    const int tc   = lane & 3;

    const float* At = A + (size_t)bm * K;
    const float* Bt = B + (size_t)bn * K;
    const int nk = K >> 5;

    auto load_stage = [&](int st, int kc) {
        const uint32_t so = sbase + (uint32_t)(st * STAGEF * 4);
#pragma unroll
        for (int i = 0; i < 4; i++) {
            int u = tid + i * 256;
            int row = u >> 3;
            int seg = (u & 7) * 4;
            cp16(so + (uint32_t)((row * SSTRIDE + seg) * 4),
                 At + (size_t)row * K + kc * 32 + seg);
            cp16(so + (uint32_t)((TILEF + row * SSTRIDE + seg) * 4),
                 Bt + (size_t)row * K + kc * 32 + seg);
        }
        asm volatile("cp.async.commit_group;" ::: "memory");
    };

    float c[4][4][4];
#pragma unroll
    for (int mf = 0; mf < 4; mf++)
#pragma unroll
        for (int nf = 0; nf < 4; nf++)
#pragma unroll
            for (int q = 0; q < 4; q++) c[mf][nf][q] = 0.0f;

    load_stage(0, 0);
    load_stage(1, 1);

    for (int s = 0; s < nk; ++s) {
        if (s + 1 < nk) asm volatile("cp.async.wait_group 1;" ::: "memory");
        else            asm volatile("cp.async.wait_group 0;" ::: "memory");
        __syncthreads();
        if (s + 2 < nk) load_stage((s + 2) % 3, s + 2);

        const float* As = smf + (s % 3) * STAGEF;
        const float* Bs = As + TILEF;

#pragma unroll
        for (int kk = 0; kk < 4; kk++) {
            const int kb = kk * 8;
            uint32_t ah[4][4], bh[4][2];
#pragma unroll
            for (int mf = 0; mf < 4; mf++) {
                const int r0 = wm * 64 + mf * 16 + tr;
                ah[mf][0] = tf32_hi(As[r0 * SSTRIDE + kb + tc]);
                ah[mf][1] = tf32_hi(As[(r0 + 8) * SSTRIDE + kb + tc]);
                ah[mf][2] = tf32_hi(As[r0 * SSTRIDE + kb + tc + 4]);
                ah[mf][3] = tf32_hi(As[(r0 + 8) * SSTRIDE + kb + tc + 4]);
            }
#pragma unroll
            for (int nf = 0; nf < 4; nf++) {
                const int n0 = wn * 32 + nf * 8 + tr;
                bh[nf][0] = tf32_hi(Bs[n0 * SSTRIDE + kb + tc]);
                bh[nf][1] = tf32_hi(Bs[n0 * SSTRIDE + kb + tc + 4]);
            }
#pragma unroll
            for (int mf = 0; mf < 4; mf++)
#pragma unroll
                for (int nf = 0; nf < 4; nf++)
                    mma8_tf32(c[mf][nf], ah[mf][0], ah[mf][1], ah[mf][2], ah[mf][3],
                              bh[nf][0], bh[nf][1]);
        }
    }

#pragma unroll
    for (int mf = 0; mf < 4; mf++) {
        const int r0g = bm + wm * 64 + mf * 16 + tr;
#pragma unroll
        for (int nf = 0; nf < 4; nf++) {
            const int cg = bn + wn * 32 + nf * 8 + 2 * tc;
            float bb0 = bias[cg], bb1 = bias[cg + 1];
            float v0 = fmaxf(c[mf][nf][0] + bb0, 0.0f);
            float v1 = fmaxf(c[mf][nf][1] + bb1, 0.0f);
            float v2 = fmaxf(c[mf][nf][2] + bb0, 0.0f);
            float v3 = fmaxf(c[mf][nf][3] + bb1, 0.0f);
            *(float2*)&C[(size_t)r0g * Ntot + cg]       = make_float2(v0, v1);
            *(float2*)&C[(size_t)(r0g + 8) * Ntot + cg] = make_float2(v2, v3);
        }
    }
}

// ============================================================================
// fp16 NT GEMM tile: 4-stage pipeline (fallback + dense k4 paths).
// ============================================================================
#define SSW      20
#define HTILEW   (128 * SSW)
#define HSTAGEW  (2 * HTILEW)
#define HGEMM_SMEM_BYTES (4 * HSTAGEW * 4)   // 81920 B

template <bool ROWSCALE, bool FP16OUT>
__device__ void gemm16_tile(
    int Ntot, int K,
    const __half* __restrict__ A, const __half* __restrict__ B,
    float* __restrict__ C, __half* __restrict__ Dh,
    const float* __restrict__ rowscale,
    int bm, int bn)
{
    extern __shared__ uint32_t smw[];
    const uint32_t sbase = (uint32_t)__cvta_generic_to_shared(smw);
    const int tid  = threadIdx.x;
    const int wid  = tid >> 5;
    const int lane = tid & 31;
    const int wm   = wid & 1;
    const int wn   = wid >> 1;
    const int tr   = lane >> 2;
    const int tc   = lane & 3;

    const __half* At = A + (size_t)bm * K;
    const __half* Bt = B + (size_t)bn * K;
    const int nk = K >> 5;

    const int q = lane >> 3;
    const int rsub = lane & 7;
    const int arow = wm * 64 + rsub + (q & 1) * 8;
    const int acolw = (q >> 1) * 4;
    const int brow = wn * 32 + rsub + (q >> 1) * 8;
    const int bcolw = (q & 1) * 4;

    auto load_stage = [&](int st, int kc) {
        const uint32_t so = sbase + (uint32_t)(st * HSTAGEW * 4);
#pragma unroll
        for (int i = 0; i < 2; i++) {
            int u = tid + i * 256;
            int row = u >> 2;
            int seg = (u & 3) * 4;
            cp16(so + (uint32_t)((row * SSW + seg) * 4),
                 At + (size_t)row * K + kc * 32 + seg * 2);
            cp16(so + (uint32_t)((HTILEW + row * SSW + seg) * 4),
                 Bt + (size_t)row * K + kc * 32 + seg * 2);
        }
        asm volatile("cp.async.commit_group;" ::: "memory");
    };

    float c[4][4][4];
#pragma unroll
    for (int mf = 0; mf < 4; mf++)
#pragma unroll
        for (int nf = 0; nf < 4; nf++)
#pragma unroll
            for (int qq = 0; qq < 4; qq++) c[mf][nf][qq] = 0.0f;

    load_stage(0, 0);
    load_stage(1, 1);
    load_stage(2, 2);

    for (int s = 0; s < nk; ++s) {
        if (s + 2 < nk)      asm volatile("cp.async.wait_group 2;" ::: "memory");
        else if (s + 1 < nk) asm volatile("cp.async.wait_group 1;" ::: "memory");
        else                 asm volatile("cp.async.wait_group 0;" ::: "memory");
        __syncthreads();
        if (s + 3 < nk) load_stage((s + 3) & 3, s + 3);

        const uint32_t stage = sbase + (uint32_t)((s & 3) * HSTAGEW * 4);
        const uint32_t aAddr0 = stage + (uint32_t)((arow * SSW + acolw) * 4);
        const uint32_t bAddr0 = stage + (uint32_t)((HTILEW + brow * SSW + bcolw) * 4);

#pragma unroll
        for (int kk = 0; kk < 2; kk++) {
            const uint32_t kboff = (uint32_t)(kk * 8 * 4);
            uint32_t a[4][4], b[4][2];
#pragma unroll
            for (int mf = 0; mf < 4; mf++)
                ldmx4(a[mf][0], a[mf][1], a[mf][2], a[mf][3],
                      aAddr0 + kboff + (uint32_t)(mf * 16 * SSW * 4));
#pragma unroll
            for (int nf2 = 0; nf2 < 2; nf2++)
                ldmx4(b[2 * nf2][0], b[2 * nf2][1], b[2 * nf2 + 1][0], b[2 * nf2 + 1][1],
                      bAddr0 + kboff + (uint32_t)(nf2 * 16 * SSW * 4));
#pragma unroll
            for (int mf = 0; mf < 4; mf++)
#pragma unroll
                for (int nf = 0; nf < 4; nf++)
                    mma16_f16(c[mf][nf], a[mf][0], a[mf][1], a[mf][2], a[mf][3],
                              b[nf][0], b[nf][1]);
        }
    }

#pragma unroll
    for (int mf = 0; mf < 4; mf++) {
        const int r0g = bm + wm * 64 + mf * 16 + tr;
        const float rs0 = ROWSCALE ? rowscale[r0g] : 1.0f;
        const float rs1 = ROWSCALE ? rowscale[r0g + 8] : 1.0f;
#pragma unroll
        for (int nf = 0; nf < 4; nf++) {
            const int cg = bn + wn * 32 + nf * 8 + 2 * tc;
            float v0 = c[mf][nf][0], v1 = c[mf][nf][1];
            float v2 = c[mf][nf][2], v3 = c[mf][nf][3];
            if (ROWSCALE) { v0 *= rs0; v1 *= rs0; v2 *= rs1; v3 *= rs1; }
            if (FP16OUT) {
                *(uint32_t*)&Dh[(size_t)r0g * Ntot + cg]       = pack_half2(v0, v1);
                *(uint32_t*)&Dh[(size_t)(r0g + 8) * Ntot + cg] = pack_half2(v2, v3);
            } else {
                *(float2*)&C[(size_t)r0g * Ntot + cg]       = make_float2(v0, v1);
                *(float2*)&C[(size_t)(r0g + 8) * Ntot + cg] = make_float2(v2, v3);
            }
        }
    }
}

// ============================================================================
// int8 NT GEMM for addressing stats: logits = (x8 @ mn8^T)/127^2.
// Epilogue computes per-row (max, sumexp) over this CTA's 128 cols and
// writes g_stats[row*4 + tilecol]. No logit output. K-chunk = 64 int8 (same
// 64B-row geometry as the fp16 kernel).
// ============================================================================
__global__ void __launch_bounds__(256, 2) gemm3s8_kernel() {
    extern __shared__ uint32_t smw[];
    __shared__ float red[2][4][64];
    const uint32_t sbase = (uint32_t)__cvta_generic_to_shared(smw);
    const int b    = blockIdx.x;
    const int bm   = (b >> 2) * 128;
    const int bt   = b & 3;          // tile col index
    const int bn0  = bt * 128;
    const int tid  = threadIdx.x;
    const int wid  = tid >> 5;
    const int lane = tid & 31;
    const int wm   = wid & 1;
    const int wn   = wid >> 1;
    const int tr   = lane >> 2;
    const int tc   = lane & 3;

    if (bt == 0 && tid == 0) g_bflag[b >> 2] = 0;

    const char* At = g_x8 + (size_t)bm * SPATIAL;
    const char* Bt = g_mn8 + (size_t)bn0 * SPATIAL;
    const int nk = SPATIAL >> 6;     // 16 chunks of 64 int8

    const int q = lane >> 3;
    const int rsub = lane & 7;
    const int arow = wm * 64 + rsub + (q & 1) * 8;
    const int acolw = (q >> 1) * 4;
    const int brow = wn * 32 + rsub + (q >> 1) * 8;
    const int bcolw = (q & 1) * 4;

    auto load_stage = [&](int st, int kc) {
        const uint32_t so = sbase + (uint32_t)(st * HSTAGEW * 4);
#pragma unroll
        for (int i = 0; i < 2; i++) {
            int u = tid + i * 256;
            int row = u >> 2;
            int seg = (u & 3) * 4;   // word seg -> 16B
            cp16(so + (uint32_t)((row * SSW + seg) * 4),
                 At + (size_t)row * SPATIAL + kc * 64 + seg * 4);
            cp16(so + (uint32_t)((HTILEW + row * SSW + seg) * 4),
                 Bt + (size_t)row * SPATIAL + kc * 64 + seg * 4);
        }
        asm volatile("cp.async.commit_group;" ::: "memory");
    };

    int c[4][4][4];
#pragma unroll
    for (int mf = 0; mf < 4; mf++)
#pragma unroll
        for (int nf = 0; nf < 4; nf++)
#pragma unroll
            for (int qq = 0; qq < 4; qq++) c[mf][nf][qq] = 0;

    load_stage(0, 0);
    load_stage(1, 1);
    load_stage(2, 2);

    for (int s = 0; s < nk; ++s) {
        if (s + 2 < nk)      asm volatile("cp.async.wait_group 2;" ::: "memory");
        else if (s + 1 < nk) asm volatile("cp.async.wait_group 1;" ::: "memory");
        else                 asm volatile("cp.async.wait_group 0;" ::: "memory");
        __syncthreads();
        if (s + 3 < nk) load_stage((s + 3) & 3, s + 3);

        const uint32_t stage = sbase + (uint32_t)((s & 3) * HSTAGEW * 4);
        const uint32_t aAddr0 = stage + (uint32_t)((arow * SSW + acolw) * 4);
        const uint32_t bAddr0 = stage + (uint32_t)((HTILEW + brow * SSW + bcolw) * 4);

#pragma unroll
        for (int kk = 0; kk < 2; kk++) {         // two k32 slabs per 64B chunk
            const uint32_t kboff = (uint32_t)(kk * 8 * 4);
            uint32_t a[4][4], bfrag[4][2];
#pragma unroll
            for (int mf = 0; mf < 4; mf++)
                ldmx4(a[mf][0], a[mf][1], a[mf][2], a[mf][3],
                      aAddr0 + kboff + (uint32_t)(mf * 16 * SSW * 4));
#pragma unroll
            for (int nf2 = 0; nf2 < 2; nf2++)
                ldmx4(bfrag[2 * nf2][0], bfrag[2 * nf2][1],
                      bfrag[2 * nf2 + 1][0], bfrag[2 * nf2 + 1][1],
                      bAddr0 + kboff + (uint32_t)(nf2 * 16 * SSW * 4));
#pragma unroll
            for (int mf = 0; mf < 4; mf++)
#pragma unroll
                for (int nf = 0; nf < 4; nf++)
                    mma32_s8(c[mf][nf], a[mf][0], a[mf][1], a[mf][2], a[mf][3],
                             bfrag[nf][0], bfrag[nf][1]);
        }
    }

    // --- stats epilogue: per-row max, then sumexp, over this CTA's 128 cols ---
    const float qs = 1.0f / 16129.0f;   // 1/127^2
    float Mrow[4][2];
    // max phase
#pragma unroll
    for (int mf = 0; mf < 4; mf++)
#pragma unroll
        for (int h = 0; h < 2; h++) {
            float mx = -INFINITY;
#pragma unroll
            for (int nf = 0; nf < 4; nf++) {
                mx = fmaxf(mx, (float)c[mf][nf][2 * h] * qs);
                mx = fmaxf(mx, (float)c[mf][nf][2 * h + 1] * qs);
            }
            mx = fmaxf(mx, __shfl_xor_sync(0xffffffffu, mx, 1));
            mx = fmaxf(mx, __shfl_xor_sync(0xffffffffu, mx, 2));
            if (tc == 0) red[wm][wn][mf * 16 + tr + 8 * h] = mx;
            Mrow[mf][h] = mx;   // placeholder; finalized below
        }
    __syncthreads();
#pragma unroll
    for (int mf = 0; mf < 4; mf++)
#pragma unroll
        for (int h = 0; h < 2; h++) {
            const int lr = mf * 16 + tr + 8 * h;
            float mx = red[wm][0][lr];
            mx = fmaxf(mx, red[wm][1][lr]);
            mx = fmaxf(mx, red[wm][2][lr]);
            mx = fmaxf(mx, red[wm][3][lr]);
            Mrow[mf][h] = mx;
        }
    __syncthreads();
    // sumexp phase
#pragma unroll
    for (int mf = 0; mf < 4; mf++)
#pragma unroll
        for (int h = 0; h < 2; h++) {
            float sm = 0.0f;
#pragma unroll
            for (int nf = 0; nf < 4; nf++) {
                sm += expf((float)c[mf][nf][2 * h] * qs - Mrow[mf][h]);
                sm += expf((float)c[mf][nf][2 * h + 1] * qs - Mrow[mf][h]);
            }
            sm += __shfl_xor_sync(0xffffffffu, sm, 1);
            sm += __shfl_xor_sync(0xffffffffu, sm, 2);
            if (tc == 0) red[wm][wn][mf * 16 + tr + 8 * h] = sm;
        }
    __syncthreads();
    if (wn == 0 && tc == 0) {
#pragma unroll
        for (int mf = 0; mf < 4; mf++)
#pragma unroll
            for (int h = 0; h < 2; h++) {
                const int lr = mf * 16 + tr + 8 * h;
                float S = red[wm][0][lr] + red[wm][1][lr] +
                          red[wm][2][lr] + red[wm][3][lr];
                g_stats[(size_t)(bm + wm * 64 + lr) * 4 + bt] =
                    make_float2(Mrow[mf][h], S);
            }
    }
}

// ============================================================================
// Flag + zero kernel: merge 4 tile-stats per row; survivor (conservative) ->
// set block flag & leave row to the exact fallback; else write f32+fp16 zeros.
// Warp per row.
// ============================================================================
__global__ __launch_bounds__(256) void flagzero_kernel(float* __restrict__ att) {
    const int row  = blockIdx.x * 8 + (threadIdx.x >> 5);
    const int lane = threadIdx.x & 31;
    int surv = 0;
    if (lane == 0) {
        float2 p0 = g_stats[(size_t)row * 4 + 0];
        float2 p1 = g_stats[(size_t)row * 4 + 1];
        float2 p2 = g_stats[(size_t)row * 4 + 2];
        float2 p3 = g_stats[(size_t)row * 4 + 3];
        float M = fmaxf(fmaxf(p0.x, p1.x), fmaxf(p2.x, p3.x));
        float S = p0.y * expf(p0.x - M) + p1.y * expf(p1.x - M)
                + p2.y * expf(p2.x - M) + p3.y * expf(p3.x - M);
        // survivor possible iff p_max = 1/S > SHRINK/1.05  <=>  S < 420
        surv = (S < 420.0f) ? 1 : 0;
        if (surv) atomicOr(&g_bflag[row >> 7], 1);
    }
    surv = __shfl_sync(0xffffffffu, surv, 0);
    if (surv) return;     // exact fallback will write this block's rows
    float4 z4 = make_float4(0.f, 0.f, 0.f, 0.f);
    uint2  z2 = make_uint2(0u, 0u);
    float4* pf = (float4*)(att + (size_t)row * MDIM);
    uint2*  ph = (uint2*)(g_atth + (size_t)row * MDIM);
#pragma unroll
    for (int i = 0; i < 4; i++) {
        pf[lane + 32 * i] = z4;
        ph[lane + 32 * i] = z2;
    }
}

// ============================================================================
// Fallback 1: exact fp16 logits for flagged row-blocks.
// ============================================================================
__global__ void __launch_bounds__(256, 2) fb_logits_kernel() {
    const int b  = blockIdx.x;
    const int rb = b >> 2;
    if (g_bflag[rb] == 0) return;
    gemm16_tile<true, true>(MDIM, SPATIAL, g_xh, g_mnh, nullptr, g_atth,
                            g_invnorm, rb * 128, (b & 3) * 128);
}

// ============================================================================
// Fallback 2: exact softmax+shrink+renorm for flagged blocks.
// ============================================================================
__global__ __launch_bounds__(256) void fb_softmax_kernel(float* __restrict__ att) {
    const int row = blockIdx.x * 8 + (threadIdx.x >> 5);
    if (g_bflag[row >> 7] == 0) return;
    const int lane = threadIdx.x & 31;
    uint2*  ph = (uint2*)(g_atth + (size_t)row * MDIM);
    float4* pf = (float4*)(att + (size_t)row * MDIM);
    float f[16];
#pragma unroll
    for (int i = 0; i < 4; i++) {
        uint2 u = ph[lane + 32 * i];
        __half2 h0 = *reinterpret_cast<__half2*>(&u.x);
        __half2 h1 = *reinterpret_cast<__half2*>(&u.y);
        float2 a = __half22float2(h0), bb = __half22float2(h1);
        f[4 * i + 0] = a.x;  f[4 * i + 1] = a.y;
        f[4 * i + 2] = bb.x; f[4 * i + 3] = bb.y;
    }
    float m = -INFINITY;
#pragma unroll
    for (int i = 0; i < 16; i++) m = fmaxf(m, f[i]);
    m = warp_max(m);
    float s = 0.0f;
#pragma unroll
    for (int i = 0; i < 16; i++) { f[i] = expf(f[i] - m); s += f[i]; }
    s = warp_sum(s);
    const float inv = 1.0f / s;
    float t = 0.0f;
#pragma unroll
    for (int i = 0; i < 16; i++) {
        f[i] = fmaxf(f[i] * inv - 0.0025f, 0.0f);
        t += f[i];
    }
    t = warp_sum(t);
    const float inv2 = 1.0f / fmaxf(t, 1e-12f);
#pragma unroll
    for (int i = 0; i < 4; i++) {
        float v0 = f[4 * i + 0] * inv2, v1 = f[4 * i + 1] * inv2;
        float v2 = f[4 * i + 2] * inv2, v3 = f[4 * i + 3] * inv2;
        pf[lane + 32 * i] = make_float4(v0, v1, v2, v3);
        ph[lane + 32 * i] = make_uint2(pack_half2(v0, v1), pack_half2(v2, v3));
    }
}

// ============================================================================
// Fused input processing: copy x -> input_flat, fp16(x) -> g_xh,
// int8(x*invnorm) -> g_x8, invnorm.
// ============================================================================
__device__ void input_rows(const float* __restrict__ x, float* __restrict__ inflat,
                           int gwarp, int nwarps, int base, int count) {
    const int lane = threadIdx.x & 31;
    for (int row = base + gwarp; row < base + count; row += nwarps) {
        const float4* p = (const float4*)(x + (size_t)row * SPATIAL);
        float4* of = (float4*)(inflat + (size_t)row * SPATIAL);
        uint2*  xo = (uint2*)(g_xh + (size_t)row * SPATIAL);
        char4*  x8 = (char4*)(g_x8 + (size_t)row * SPATIAL);
        float4 v[8];
        float s = 0.0f;
#pragma unroll
        for (int i = 0; i < 8; i++) {
            v[i] = p[lane + 32 * i];
            s += v[i].x * v[i].x + v[i].y * v[i].y + v[i].z * v[i].z + v[i].w * v[i].w;
            of[lane + 32 * i] = v[i];
            xo[lane + 32 * i] = make_uint2(pack_half2(v[i].x, v[i].y),
                                           pack_half2(v[i].z, v[i].w));
        }
        s = warp_sum(s);
        const float inv = 1.0f / fmaxf(sqrtf(s), 1e-12f);
        if (lane == 0) g_invnorm[row] = inv;
#pragma unroll
        for (int i = 0; i < 8; i++)
            x8[lane + 32 * i] = make_char4(q8(v[i].x * inv), q8(v[i].y * inv),
                                           q8(v[i].z * inv), q8(v[i].w * inv));
    }
}

// K1: MLP1 (16 CTAs) + input rows 0..8191 (132 CTAs)
__global__ void __launch_bounds__(256, 1) k1_mlp1_input(
    const float* __restrict__ memory, const float* __restrict__ w1,
    const float* __restrict__ b1, const float* __restrict__ x,
    float* __restrict__ inflat)
{
    const int b = blockIdx.x;
    if (b < 16) {
        mlp_tile(HIDDIM, SPATIAL, memory, w1, g_h, b1, (b >> 2) * 128, (b & 3) * 128);
    } else {
        const int gwarp = (b - 16) * 8 + (threadIdx.x >> 5);
        input_rows(x, inflat, gwarp, 132 * 8, 0, 8192);
    }
}

// K2: MLP2 (32 CTAs) + input rows 8192..16383 (116 CTAs)
__global__ void __launch_bounds__(256, 1) k2_mlp2_input(
    const float* __restrict__ w2, const float* __restrict__ b2,
    const float* __restrict__ x, float* __restrict__ inflat)
{
    const int b = blockIdx.x;
    if (b < 32) {
        mlp_tile(SPATIAL, HIDDIM, g_h, w2, g_memproc, b2, (b >> 3) * 128, (b & 7) * 128);
    } else {
        const int gwarp = (b - 32) * 8 + (threadIdx.x >> 5);
        input_rows(x, inflat, gwarp, 116 * 8, 8192, 8192);
    }
}

// ============================================================================
// rownorm: f32 -> d_out, fp16 -> g_mnh, fp16^T -> g_mnTh, int8 -> g_mn8.
// ============================================================================
__global__ __launch_bounds__(256) void rownorm_t_kernel(float* __restrict__ dst) {
    __shared__ float sm[8];
    const int row  = blockIdx.x;
    const int tid  = threadIdx.x;
    const int lane = tid & 31;
    const int w    = tid >> 5;
    const float4* p = (const float4*)(g_memproc + (size_t)row * SPATIAL);
    float4 v = p[tid];
    float s = v.x * v.x + v.y * v.y + v.z * v.z + v.w * v.w;
    s = warp_sum(s);
    if (lane == 0) sm[w] = s;
    __syncthreads();
    float tot = 0.0f;
#pragma unroll
    for (int i = 0; i < 8; i++) tot += sm[i];
    const float sc = 1.0f / fmaxf(sqrtf(tot), 1e-12f);
    float4 o = make_float4(v.x * sc, v.y * sc, v.z * sc, v.w * sc);
    ((float4*)(dst + (size_t)row * SPATIAL))[tid] = o;
    ((uint2*)(g_mnh + (size_t)row * SPATIAL))[tid] =
        make_uint2(pack_half2(o.x, o.y), pack_half2(o.z, o.w));
    ((char4*)(g_mn8 + (size_t)row * SPATIAL))[tid] =
        make_char4(q8(o.x), q8(o.y), q8(o.z), q8(o.w));
    g_mnTh[(size_t)(4 * tid + 0) * MDIM + row] = __float2half_rn(o.x);
    g_mnTh[(size_t)(4 * tid + 1) * MDIM + row] = __float2half_rn(o.y);
    g_mnTh[(size_t)(4 * tid + 2) * MDIM + row] = __float2half_rn(o.z);
    g_mnTh[(size_t)(4 * tid + 3) * MDIM + row] = __float2half_rn(o.w);
}

// ============================================================================
// K4: tail blocks (chanmean+bcast, 128) first, then GEMM4 (1024 blocks).
// Sparsity-aware (unchanged from R14).
// ============================================================================
__global__ void __launch_bounds__(256, 2) k4_gemm4_tail(
    float* __restrict__ outp, float* __restrict__ attsp)
{
    const int b = blockIdx.x;
    const int t = threadIdx.x;
    if (b >= 128) {
        const int g = b - 128;
        const int rb = g >> 3;
        const int bm = rb * 128;
        const int bn = (g & 7) * 128;
        if (g_bflag[rb] == 0) {
            float4 z = make_float4(0.f, 0.f, 0.f, 0.f);
#pragma unroll
            for (int i = 0; i < 16; i++) {
                int u = t + i * 256;
                int r = u >> 5;
                int c4 = u & 31;
                ((float4*)&outp[(size_t)(bm + r) * SPATIAL + bn])[c4] = z;
            }
            return;
        }
        gemm16_tile<false, false>(SPATIAL, MDIM, g_atth, g_mnTh, outp, nullptr,
                                  nullptr, bm, bn);
        return;
    }
    const int n  = b >> 2;
    const int mg = b & 3;
    const int any = g_bflag[4 * n] | g_bflag[4 * n + 1] |
                    g_bflag[4 * n + 2] | g_bflag[4 * n + 3];
    float* dst0 = attsp + ((size_t)(n * MDIM + mg * 128)) * SPATIAL;
    if (any == 0) {
        float4 z = make_float4(0.f, 0.f, 0.f, 0.f);
        for (int m2 = 0; m2 < 128; m2++)
            ((float4*)(dst0 + (size_t)m2 * SPATIAL))[t] = z;
        return;
    }
    extern __shared__ float sf[];
    const int m  = t & 127;
    const int ch = t >> 7;
    const __half* base = g_atth + ((size_t)(n * 512 + ch * 256)) * MDIM + mg * 128 + m;
    float s = 0.0f;
#pragma unroll 4
    for (int c = 0; c < 256; c++) s += __half2float(base[(size_t)c * MDIM]);
    sf[t] = s;
    __syncthreads();
    if (t < 128) sf[256 + t] = (sf[t] + sf[t + 128]) * (1.0f / 512.0f);
    __syncthreads();
    for (int m2 = 0; m2 < 128; m2++) {
        const float v = sf[256 + m2];
        ((float4*)(dst0 + (size_t)m2 * SPATIAL))[t] = make_float4(v, v, v, v);
    }
}

// ============================================================================
extern "C" void kernel_launch(void* const* d_in, const int* in_sizes, int n_in,
                              void* d_out, int out_size) {
    (void)in_sizes; (void)n_in; (void)out_size;
    const float* x      = (const float*)d_in[0];
    const float* memory = (const float*)d_in[1];
    const float* w1     = (const float*)d_in[2];
    const float* b1     = (const float*)d_in[3];
    const float* w2     = (const float*)d_in[4];
    const float* b2     = (const float*)d_in[5];

    float* out = (float*)d_out;
    float* out_output  = out + OFF_OUTPUT;
    float* out_attsp   = out + OFF_ATTSP;
    float* out_inflat  = out + OFF_INFLAT;
    float* out_memnorm = out + OFF_MEMNORM;
    float* out_att     = out + OFF_ATT;

    cudaFuncSetAttribute((const void*)k1_mlp1_input,
                         cudaFuncAttributeMaxDynamicSharedMemorySize, GEMM_SMEM_BYTES);
    cudaFuncSetAttribute((const void*)k2_mlp2_input,
                         cudaFuncAttributeMaxDynamicSharedMemorySize, GEMM_SMEM_BYTES);
    cudaFuncSetAttribute((const void*)gemm3s8_kernel,
                         cudaFuncAttributeMaxDynamicSharedMemorySize, HGEMM_SMEM_BYTES);
    cudaFuncSetAttribute((const void*)fb_logits_kernel,
                         cudaFuncAttributeMaxDynamicSharedMemorySize, HGEMM_SMEM_BYTES);
    cudaFuncSetAttribute((const void*)k4_gemm4_tail,
                         cudaFuncAttributeMaxDynamicSharedMemorySize, HGEMM_SMEM_BYTES);

    // L1: MLP layer 1 || input processing (rows 0..8191)
    k1_mlp1_input<<<148, 256, GEMM_SMEM_BYTES>>>(memory, w1, b1, x, out_inflat);
    // L2: MLP layer 2 || input processing (rows 8192..16383)
    k2_mlp2_input<<<148, 256, GEMM_SMEM_BYTES>>>(w2, b2, x, out_inflat);
    // L3: memory_norm (f32 + fp16 + fp16^T + int8)
    rownorm_t_kernel<<<MDIM, 256>>>(out_memnorm);
    // L4: int8 addressing GEMM -> per-row softmax stats (+ flag reset)
    gemm3s8_kernel<<<512, 256, HGEMM_SMEM_BYTES>>>();
    // L5: merge stats -> survivor flags; zero att (f32+fp16) for clear rows
    flagzero_kernel<<<R_ROWS / 8, 256>>>(out_att);
    // L6: exact fp16 logits for flagged blocks (no-op when none)
    fb_logits_kernel<<<512, 256, HGEMM_SMEM_BYTES>>>();
    // L7: exact softmax for flagged blocks (no-op when none)
    fb_softmax_kernel<<<R_ROWS / 8, 256>>>(out_att);
    // L8: output GEMM (sparsity-aware) + fused channel-mean/broadcast
    k4_gemm4_tail<<<1152, 256, HGEMM_SMEM_BYTES>>>(out_output, out_attsp);
}

// round 16
// speedup vs baseline: 1.4434x; 1.4434x over previous
#include <cuda_runtime.h>
#include <cuda_fp16.h>
#include <cstdint>
#include <math.h>

// Problem constants
#define R_ROWS  16384   // N*C
#define SPATIAL 1024    // H*W
#define MDIM    512     // mem_dim
#define HIDDIM  512     // spatial/2

// d_out section offsets (floats)
#define OFF_OUTPUT   ((size_t)0)
#define OFF_ATTSP    ((size_t)16777216)
#define OFF_INFLAT   ((size_t)33554432)
#define OFF_MEMNORM  ((size_t)50331648)
#define OFF_ATT      ((size_t)50855936)

// Device scratch (allocation-free)
__device__ float  g_h[MDIM * HIDDIM];
__device__ float  g_memproc[MDIM * SPATIAL];
__device__ float  g_invnorm[R_ROWS];
__device__ __half g_xh[(size_t)R_ROWS * SPATIAL];    // fp16 x
__device__ __half g_mnh[MDIM * SPATIAL];             // fp16 memory_norm
__device__ __half g_mnTh[SPATIAL * MDIM];            // fp16 memory_norm^T
__device__ __half g_atth[(size_t)R_ROWS * MDIM];     // fp16 logits/att (flagged blocks)
__device__ float2 g_stats[(size_t)R_ROWS * 4];       // per-row per-tile (max, sumexp)
__device__ int    g_bflag[R_ROWS / 128];             // per-128-row survivor flags

// ============================================================================
// mma.sync helpers (sm_80+ — base compute_103 target safe)
// ============================================================================
__device__ __forceinline__ void mma8_tf32(float* c, uint32_t a0, uint32_t a1,
                                          uint32_t a2, uint32_t a3,
                                          uint32_t b0, uint32_t b1) {
    asm volatile(
        "mma.sync.aligned.m16n8k8.row.col.f32.tf32.tf32.f32 "
        "{%0,%1,%2,%3}, {%4,%5,%6,%7}, {%8,%9}, {%0,%1,%2,%3};"
        : "+f"(c[0]), "+f"(c[1]), "+f"(c[2]), "+f"(c[3])
        : "r"(a0), "r"(a1), "r"(a2), "r"(a3), "r"(b0), "r"(b1));
}

__device__ __forceinline__ void mma16_f16(float* c, uint32_t a0, uint32_t a1,
                                          uint32_t a2, uint32_t a3,
                                          uint32_t b0, uint32_t b1) {
    asm volatile(
        "mma.sync.aligned.m16n8k16.row.col.f32.f16.f16.f32 "
        "{%0,%1,%2,%3}, {%4,%5,%6,%7}, {%8,%9}, {%0,%1,%2,%3};"
        : "+f"(c[0]), "+f"(c[1]), "+f"(c[2]), "+f"(c[3])
        : "r"(a0), "r"(a1), "r"(a2), "r"(a3), "r"(b0), "r"(b1));
}

__device__ __forceinline__ void ldmx4(uint32_t& r0, uint32_t& r1,
                                      uint32_t& r2, uint32_t& r3, uint32_t addr) {
    asm volatile("ldmatrix.sync.aligned.m8n8.x4.shared.b16 {%0,%1,%2,%3}, [%4];"
                 : "=r"(r0), "=r"(r1), "=r"(r2), "=r"(r3) : "r"(addr));
}

__device__ __forceinline__ uint32_t tf32_hi(float x) {
    uint32_t h;
    asm("cvt.rna.tf32.f32 %0, %1;" : "=r"(h) : "f"(x));
    return h;
}

__device__ __forceinline__ void cp16(uint32_t dst, const void* src) {
    asm volatile("cp.async.cg.shared.global [%0], [%1], 16;" :: "r"(dst), "l"(src));
}

__device__ __forceinline__ uint32_t pack_half2(float a, float b) {
    __half2 h = __floats2half2_rn(a, b);
    return *reinterpret_cast<uint32_t*>(&h);
}

__device__ __forceinline__ float warp_sum(float v) {
#pragma unroll
    for (int o = 16; o > 0; o >>= 1) v += __shfl_xor_sync(0xffffffffu, v, o);
    return v;
}
__device__ __forceinline__ float warp_max(float v) {
#pragma unroll
    for (int o = 16; o > 0; o >>= 1) v = fmaxf(v, __shfl_xor_sync(0xffffffffu, v, o));
    return v;
}

// ============================================================================
// tf32 NT GEMM tile (device fn) — precision-critical MLP path.
// ============================================================================
#define SSTRIDE 36
#define TILEF   (128 * SSTRIDE)
#define STAGEF  (2 * TILEF)
#define GEMM_SMEM_BYTES (3 * STAGEF * 4)

__device__ void mlp_tile(
    int Ntot, int K,
    const float* __restrict__ A, const float* __restrict__ B,
    float* __restrict__ C, const float* __restrict__ bias,
    int bm, int bn)
{
    extern __shared__ float smf[];
    const uint32_t sbase = (uint32_t)__cvta_generic_to_shared(smf);
    const int tid  = threadIdx.x;
    const int wid  = tid >> 5;
    const int lane = tid & 31;
    const int wm   = wid & 1;
    const int wn   = wid >> 1;
    const int tr   = lane >> 2;
    const int tc   = lane & 3;

    const float* At = A + (size_t)bm * K;
    const float* Bt = B + (size_t)bn * K;
    const int nk = K >> 5;

    auto load_stage = [&](int st, int kc) {
        const uint32_t so = sbase + (uint32_t)(st * STAGEF * 4);
#pragma unroll
        for (int i = 0; i < 4; i++) {
            int u = tid + i * 256;
            int row = u >> 3;
            int seg = (u & 7) * 4;
            cp16(so + (uint32_t)((row * SSTRIDE + seg) * 4),
                 At + (size_t)row * K + kc * 32 + seg);
            cp16(so + (uint32_t)((TILEF + row * SSTRIDE + seg) * 4),
                 Bt + (size_t)row * K + kc * 32 + seg);
        }
        asm volatile("cp.async.commit_group;" ::: "memory");
    };

    float c[4][4][4];
#pragma unroll
    for (int mf = 0; mf < 4; mf++)
#pragma unroll
        for (int nf = 0; nf < 4; nf++)
#pragma unroll
            for (int q = 0; q < 4; q++) c[mf][nf][q] = 0.0f;

    load_stage(0, 0);
    load_stage(1, 1);

    for (int s = 0; s < nk; ++s) {
        if (s + 1 < nk) asm volatile("cp.async.wait_group 1;" ::: "memory");
        else            asm volatile("cp.async.wait_group 0;" ::: "memory");
        __syncthreads();
        if (s + 2 < nk) load_stage((s + 2) % 3, s + 2);

        const float* As = smf + (s % 3) * STAGEF;
        const float* Bs = As + TILEF;

#pragma unroll
        for (int kk = 0; kk < 4; kk++) {
            const int kb = kk * 8;
            uint32_t ah[4][4], bh[4][2];
#pragma unroll
            for (int mf = 0; mf < 4; mf++) {
                const int r0 = wm * 64 + mf * 16 + tr;
                ah[mf][0] = tf32_hi(As[r0 * SSTRIDE + kb + tc]);
                ah[mf][1] = tf32_hi(As[(r0 + 8) * SSTRIDE + kb + tc]);
                ah[mf][2] = tf32_hi(As[r0 * SSTRIDE + kb + tc + 4]);
                ah[mf][3] = tf32_hi(As[(r0 + 8) * SSTRIDE + kb + tc + 4]);
            }
#pragma unroll
            for (int nf = 0; nf < 4; nf++) {
                const int n0 = wn * 32 + nf * 8 + tr;
                bh[nf][0] = tf32_hi(Bs[n0 * SSTRIDE + kb + tc]);
                bh[nf][1] = tf32_hi(Bs[n0 * SSTRIDE + kb + tc + 4]);
            }
#pragma unroll
            for (int mf = 0; mf < 4; mf++)
#pragma unroll
                for (int nf = 0; nf < 4; nf++)
                    mma8_tf32(c[mf][nf], ah[mf][0], ah[mf][1], ah[mf][2], ah[mf][3],
                              bh[nf][0], bh[nf][1]);
        }
    }

#pragma unroll
    for (int mf = 0; mf < 4; mf++) {
        const int r0g = bm + wm * 64 + mf * 16 + tr;
#pragma unroll
        for (int nf = 0; nf < 4; nf++) {
            const int cg = bn + wn * 32 + nf * 8 + 2 * tc;
            float bb0 = bias[cg], bb1 = bias[cg + 1];
            float v0 = fmaxf(c[mf][nf][0] + bb0, 0.0f);
            float v1 = fmaxf(c[mf][nf][1] + bb1, 0.0f);
            float v2 = fmaxf(c[mf][nf][2] + bb0, 0.0f);
            float v3 = fmaxf(c[mf][nf][3] + bb1, 0.0f);
            *(float2*)&C[(size_t)r0g * Ntot + cg]       = make_float2(v0, v1);
            *(float2*)&C[(size_t)(r0g + 8) * Ntot + cg] = make_float2(v2, v3);
        }
    }
}

// ============================================================================
// fp16 NT GEMM mainloop core: computes c[4][4][4] for a 128x128 tile.
// ============================================================================
#define SSW      20
#define HTILEW   (128 * SSW)
#define HSTAGEW  (2 * HTILEW)
#define HGEMM_SMEM_BYTES (4 * HSTAGEW * 4)   // 81920 B

__device__ __forceinline__ void gemm16_core(
    int K, const __half* __restrict__ At, const __half* __restrict__ Bt,
    float c[4][4][4])
{
    extern __shared__ uint32_t smw[];
    const uint32_t sbase = (uint32_t)__cvta_generic_to_shared(smw);
    const int tid  = threadIdx.x;
    const int wid  = tid >> 5;
    const int lane = tid & 31;
    const int wm   = wid & 1;
    const int wn   = wid >> 1;
    const int nk = K >> 5;

    const int q = lane >> 3;
    const int rsub = lane & 7;
    const int arow = wm * 64 + rsub + (q & 1) * 8;
    const int acolw = (q >> 1) * 4;
    const int brow = wn * 32 + rsub + (q >> 1) * 8;
    const int bcolw = (q & 1) * 4;

    auto load_stage = [&](int st, int kc) {
        const uint32_t so = sbase + (uint32_t)(st * HSTAGEW * 4);
#pragma unroll
        for (int i = 0; i < 2; i++) {
            int u = tid + i * 256;
            int row = u >> 2;
            int seg = (u & 3) * 4;
            cp16(so + (uint32_t)((row * SSW + seg) * 4),
                 At + (size_t)row * K + kc * 32 + seg * 2);
            cp16(so + (uint32_t)((HTILEW + row * SSW + seg) * 4),
                 Bt + (size_t)row * K + kc * 32 + seg * 2);
        }
        asm volatile("cp.async.commit_group;" ::: "memory");
    };

#pragma unroll
    for (int mf = 0; mf < 4; mf++)
#pragma unroll
        for (int nf = 0; nf < 4; nf++)
#pragma unroll
            for (int qq = 0; qq < 4; qq++) c[mf][nf][qq] = 0.0f;

    load_stage(0, 0);
    load_stage(1, 1);
    load_stage(2, 2);

    for (int s = 0; s < nk; ++s) {
        if (s + 2 < nk)      asm volatile("cp.async.wait_group 2;" ::: "memory");
        else if (s + 1 < nk) asm volatile("cp.async.wait_group 1;" ::: "memory");
        else                 asm volatile("cp.async.wait_group 0;" ::: "memory");
        __syncthreads();
        if (s + 3 < nk) load_stage((s + 3) & 3, s + 3);

        const uint32_t stage = sbase + (uint32_t)((s & 3) * HSTAGEW * 4);
        const uint32_t aAddr0 = stage + (uint32_t)((arow * SSW + acolw) * 4);
        const uint32_t bAddr0 = stage + (uint32_t)((HTILEW + brow * SSW + bcolw) * 4);

#pragma unroll
        for (int kk = 0; kk < 2; kk++) {
            const uint32_t kboff = (uint32_t)(kk * 8 * 4);
            uint32_t a[4][4], b[4][2];
#pragma unroll
            for (int mf = 0; mf < 4; mf++)
                ldmx4(a[mf][0], a[mf][1], a[mf][2], a[mf][3],
                      aAddr0 + kboff + (uint32_t)(mf * 16 * SSW * 4));
#pragma unroll
            for (int nf2 = 0; nf2 < 2; nf2++)
                ldmx4(b[2 * nf2][0], b[2 * nf2][1], b[2 * nf2 + 1][0], b[2 * nf2 + 1][1],
                      bAddr0 + kboff + (uint32_t)(nf2 * 16 * SSW * 4));
#pragma unroll
            for (int mf = 0; mf < 4; mf++)
#pragma unroll
                for (int nf = 0; nf < 4; nf++)
                    mma16_f16(c[mf][nf], a[mf][0], a[mf][1], a[mf][2], a[mf][3],
                              b[nf][0], b[nf][1]);
        }
    }
}

// Epilogue variants on top of gemm16_core
template <bool ROWSCALE, bool FP16OUT>
__device__ void gemm16_tile(
    int Ntot, int K,
    const __half* __restrict__ A, const __half* __restrict__ B,
    float* __restrict__ C, __half* __restrict__ Dh,
    const float* __restrict__ rowscale,
    int bm, int bn)
{
    const int tid  = threadIdx.x;
    const int wid  = tid >> 5;
    const int lane = tid & 31;
    const int wm   = wid & 1;
    const int wn   = wid >> 1;
    const int tr   = lane >> 2;
    const int tc   = lane & 3;

    float c[4][4][4];
    gemm16_core(K, A + (size_t)bm * K, B + (size_t)bn * K, c);

#pragma unroll
    for (int mf = 0; mf < 4; mf++) {
        const int r0g = bm + wm * 64 + mf * 16 + tr;
        const float rs0 = ROWSCALE ? rowscale[r0g] : 1.0f;
        const float rs1 = ROWSCALE ? rowscale[r0g + 8] : 1.0f;
#pragma unroll
        for (int nf = 0; nf < 4; nf++) {
            const int cg = bn + wn * 32 + nf * 8 + 2 * tc;
            float v0 = c[mf][nf][0], v1 = c[mf][nf][1];
            float v2 = c[mf][nf][2], v3 = c[mf][nf][3];
            if (ROWSCALE) { v0 *= rs0; v1 *= rs0; v2 *= rs1; v3 *= rs1; }
            if (FP16OUT) {
                *(uint32_t*)&Dh[(size_t)r0g * Ntot + cg]       = pack_half2(v0, v1);
                *(uint32_t*)&Dh[(size_t)(r0g + 8) * Ntot + cg] = pack_half2(v2, v3);
            } else {
                *(float2*)&C[(size_t)r0g * Ntot + cg]       = make_float2(v0, v1);
                *(float2*)&C[(size_t)(r0g + 8) * Ntot + cg] = make_float2(v2, v3);
            }
        }
    }
}

// ============================================================================
// GEMM3 with stats epilogue: rowscaled logits -> per-row (max, sumexp) for
// this CTA's 128 cols -> g_stats[row*4 + tilecol]. No logit output.
// ============================================================================
__global__ void __launch_bounds__(256, 2) gemm3_stats_kernel() {
    __shared__ float red[2][4][64];
    const int b    = blockIdx.x;
    const int bm   = (b >> 2) * 128;
    const int bt   = b & 3;
    const int tid  = threadIdx.x;
    const int wid  = tid >> 5;
    const int lane = tid & 31;
    const int wm   = wid & 1;
    const int wn   = wid >> 1;
    const int tr   = lane >> 2;
    const int tc   = lane & 3;

    if (bt == 0 && tid == 0) g_bflag[b >> 2] = 0;

    float c[4][4][4];
    gemm16_core(SPATIAL, g_xh + (size_t)bm * SPATIAL,
                g_mnh + (size_t)(bt * 128) * SPATIAL, c);

    // rowscale in-register
    float rs[4][2];
#pragma unroll
    for (int mf = 0; mf < 4; mf++) {
        rs[mf][0] = g_invnorm[bm + wm * 64 + mf * 16 + tr];
        rs[mf][1] = g_invnorm[bm + wm * 64 + mf * 16 + tr + 8];
    }

    float Mrow[4][2];
    // max phase
#pragma unroll
    for (int mf = 0; mf < 4; mf++)
#pragma unroll
        for (int h = 0; h < 2; h++) {
            float mx = -INFINITY;
#pragma unroll
            for (int nf = 0; nf < 4; nf++) {
                mx = fmaxf(mx, c[mf][nf][2 * h] * rs[mf][h]);
                mx = fmaxf(mx, c[mf][nf][2 * h + 1] * rs[mf][h]);
            }
            mx = fmaxf(mx, __shfl_xor_sync(0xffffffffu, mx, 1));
            mx = fmaxf(mx, __shfl_xor_sync(0xffffffffu, mx, 2));
            if (tc == 0) red[wm][wn][mf * 16 + tr + 8 * h] = mx;
        }
    __syncthreads();
#pragma unroll
    for (int mf = 0; mf < 4; mf++)
#pragma unroll
        for (int h = 0; h < 2; h++) {
            const int lr = mf * 16 + tr + 8 * h;
            float mx = red[wm][0][lr];
            mx = fmaxf(mx, red[wm][1][lr]);
            mx = fmaxf(mx, red[wm][2][lr]);
            mx = fmaxf(mx, red[wm][3][lr]);
            Mrow[mf][h] = mx;
        }
    __syncthreads();
    // sumexp phase
#pragma unroll
    for (int mf = 0; mf < 4; mf++)
#pragma unroll
        for (int h = 0; h < 2; h++) {
            float sm = 0.0f;
#pragma unroll
            for (int nf = 0; nf < 4; nf++) {
                sm += expf(c[mf][nf][2 * h] * rs[mf][h] - Mrow[mf][h]);
                sm += expf(c[mf][nf][2 * h + 1] * rs[mf][h] - Mrow[mf][h]);
            }
            sm += __shfl_xor_sync(0xffffffffu, sm, 1);
            sm += __shfl_xor_sync(0xffffffffu, sm, 2);
            if (tc == 0) red[wm][wn][mf * 16 + tr + 8 * h] = sm;
        }
    __syncthreads();
    if (wn == 0 && tc == 0) {
#pragma unroll
        for (int mf = 0; mf < 4; mf++)
#pragma unroll
            for (int h = 0; h < 2; h++) {
                const int lr = mf * 16 + tr + 8 * h;
                float S = red[wm][0][lr] + red[wm][1][lr] +
                          red[wm][2][lr] + red[wm][3][lr];
                g_stats[(size_t)(bm + wm * 64 + lr) * 4 + bt] =
                    make_float2(Mrow[mf][h], S);
            }
    }
}

// ============================================================================
// Flag + zero: merge 4 tile-stats per row; conservative survivor test sets the
// block flag (exact fallback handles those); else write f32 att zeros.
// ============================================================================
__global__ __launch_bounds__(256) void flagzero_kernel(float* __restrict__ att) {
    const int row  = blockIdx.x * 8 + (threadIdx.x >> 5);
    const int lane = threadIdx.x & 31;
    int surv = 0;
    if (lane == 0) {
        float2 p0 = g_stats[(size_t)row * 4 + 0];
        float2 p1 = g_stats[(size_t)row * 4 + 1];
        float2 p2 = g_stats[(size_t)row * 4 + 2];
        float2 p3 = g_stats[(size_t)row * 4 + 3];
        float M = fmaxf(fmaxf(p0.x, p1.x), fmaxf(p2.x, p3.x));
        float S = p0.y * expf(p0.x - M) + p1.y * expf(p1.x - M)
                + p2.y * expf(p2.x - M) + p3.y * expf(p3.x - M);
        // survivor possible iff p_max = 1/S > SHRINK (=1/400); 5% guard band
        surv = (S < 420.0f) ? 1 : 0;
        if (surv) atomicOr(&g_bflag[row >> 7], 1);
    }
    surv = __shfl_sync(0xffffffffu, surv, 0);
    if (surv) return;
    float4 z4 = make_float4(0.f, 0.f, 0.f, 0.f);
    float4* pf = (float4*)(att + (size_t)row * MDIM);
#pragma unroll
    for (int i = 0; i < 4; i++) pf[lane + 32 * i] = z4;
}

// ============================================================================
// Fallback 1: exact fp16 logits for flagged row-blocks.
// ============================================================================
__global__ void __launch_bounds__(256, 2) fb_logits_kernel() {
    const int b  = blockIdx.x;
    const int rb = b >> 2;
    if (g_bflag[rb] == 0) return;
    gemm16_tile<true, true>(MDIM, SPATIAL, g_xh, g_mnh, nullptr, g_atth,
                            g_invnorm, rb * 128, (b & 3) * 128);
}

// ============================================================================
// Fallback 2: exact softmax+shrink+renorm for flagged blocks (f32 + fp16 out).
// ============================================================================
__global__ __launch_bounds__(256) void fb_softmax_kernel(float* __restrict__ att) {
    const int row = blockIdx.x * 8 + (threadIdx.x >> 5);
    if (g_bflag[row >> 7] == 0) return;
    const int lane = threadIdx.x & 31;
    uint2*  ph = (uint2*)(g_atth + (size_t)row * MDIM);
    float4* pf = (float4*)(att + (size_t)row * MDIM);
    float f[16];
#pragma unroll
    for (int i = 0; i < 4; i++) {
        uint2 u = ph[lane + 32 * i];
        __half2 h0 = *reinterpret_cast<__half2*>(&u.x);
        __half2 h1 = *reinterpret_cast<__half2*>(&u.y);
        float2 a = __half22float2(h0), bb = __half22float2(h1);
        f[4 * i + 0] = a.x;  f[4 * i + 1] = a.y;
        f[4 * i + 2] = bb.x; f[4 * i + 3] = bb.y;
    }
    float m = -INFINITY;
#pragma unroll
    for (int i = 0; i < 16; i++) m = fmaxf(m, f[i]);
    m = warp_max(m);
    float s = 0.0f;
#pragma unroll
    for (int i = 0; i < 16; i++) { f[i] = expf(f[i] - m); s += f[i]; }
    s = warp_sum(s);
    const float inv = 1.0f / s;
    float t = 0.0f;
#pragma unroll
    for (int i = 0; i < 16; i++) {
        f[i] = fmaxf(f[i] * inv - 0.0025f, 0.0f);
        t += f[i];
    }
    t = warp_sum(t);
    const float inv2 = 1.0f / fmaxf(t, 1e-12f);
#pragma unroll
    for (int i = 0; i < 4; i++) {
        float v0 = f[4 * i + 0] * inv2, v1 = f[4 * i + 1] * inv2;
        float v2 = f[4 * i + 2] * inv2, v3 = f[4 * i + 3] * inv2;
        pf[lane + 32 * i] = make_float4(v0, v1, v2, v3);
        ph[lane + 32 * i] = make_uint2(pack_half2(v0, v1), pack_half2(v2, v3));
    }
}

// ============================================================================
// Fused input processing: copy x -> input_flat, fp16(x) -> g_xh, invnorm.
// ============================================================================
__device__ void input_rows(const float* __restrict__ x, float* __restrict__ inflat,
                           int gwarp, int nwarps, int base, int count) {
    const int lane = threadIdx.x & 31;
    for (int row = base + gwarp; row < base + count; row += nwarps) {
        const float4* p = (const float4*)(x + (size_t)row * SPATIAL);
        float4* of = (float4*)(inflat + (size_t)row * SPATIAL);
        uint2*  xo = (uint2*)(g_xh + (size_t)row * SPATIAL);
        float s = 0.0f;
#pragma unroll
        for (int i = 0; i < 8; i++) {
            float4 v = p[lane + 32 * i];
            s += v.x * v.x + v.y * v.y + v.z * v.z + v.w * v.w;
            of[lane + 32 * i] = v;
            xo[lane + 32 * i] = make_uint2(pack_half2(v.x, v.y), pack_half2(v.z, v.w));
        }
        s = warp_sum(s);
        if (lane == 0) g_invnorm[row] = 1.0f / fmaxf(sqrtf(s), 1e-12f);
    }
}

// K1: MLP1 (16 CTAs) + input rows 0..8191 (132 CTAs)
__global__ void __launch_bounds__(256, 1) k1_mlp1_input(
    const float* __restrict__ memory, const float* __restrict__ w1,
    const float* __restrict__ b1, const float* __restrict__ x,
    float* __restrict__ inflat)
{
    const int b = blockIdx.x;
    if (b < 16) {
        mlp_tile(HIDDIM, SPATIAL, memory, w1, g_h, b1, (b >> 2) * 128, (b & 3) * 128);
    } else {
        const int gwarp = (b - 16) * 8 + (threadIdx.x >> 5);
        input_rows(x, inflat, gwarp, 132 * 8, 0, 8192);
    }
}

// K2: MLP2 (32 CTAs) + input rows 8192..16383 (116 CTAs)
__global__ void __launch_bounds__(256, 1) k2_mlp2_input(
    const float* __restrict__ w2, const float* __restrict__ b2,
    const float* __restrict__ x, float* __restrict__ inflat)
{
    const int b = blockIdx.x;
    if (b < 32) {
        mlp_tile(SPATIAL, HIDDIM, g_h, w2, g_memproc, b2, (b >> 3) * 128, (b & 7) * 128);
    } else {
        const int gwarp = (b - 32) * 8 + (threadIdx.x >> 5);
        input_rows(x, inflat, gwarp, 116 * 8, 8192, 8192);
    }
}

// ============================================================================
// rownorm: f32 -> d_out, fp16 -> g_mnh, fp16^T -> g_mnTh. Block per row.
// ============================================================================
__global__ __launch_bounds__(256) void rownorm_t_kernel(float* __restrict__ dst) {
    __shared__ float sm[8];
    const int row  = blockIdx.x;
    const int tid  = threadIdx.x;
    const int lane = tid & 31;
    const int w    = tid >> 5;
    const float4* p = (const float4*)(g_memproc + (size_t)row * SPATIAL);
    float4 v = p[tid];
    float s = v.x * v.x + v.y * v.y + v.z * v.z + v.w * v.w;
    s = warp_sum(s);
    if (lane == 0) sm[w] = s;
    __syncthreads();
    float tot = 0.0f;
#pragma unroll
    for (int i = 0; i < 8; i++) tot += sm[i];
    const float sc = 1.0f / fmaxf(sqrtf(tot), 1e-12f);
    float4 o = make_float4(v.x * sc, v.y * sc, v.z * sc, v.w * sc);
    ((float4*)(dst + (size_t)row * SPATIAL))[tid] = o;
    ((uint2*)(g_mnh + (size_t)row * SPATIAL))[tid] =
        make_uint2(pack_half2(o.x, o.y), pack_half2(o.z, o.w));
    g_mnTh[(size_t)(4 * tid + 0) * MDIM + row] = __float2half_rn(o.x);
    g_mnTh[(size_t)(4 * tid + 1) * MDIM + row] = __float2half_rn(o.y);
    g_mnTh[(size_t)(4 * tid + 2) * MDIM + row] = __float2half_rn(o.z);
    g_mnTh[(size_t)(4 * tid + 3) * MDIM + row] = __float2half_rn(o.w);
}

// ============================================================================
// K4: tail blocks (chanmean+bcast, 128) first, then GEMM4 (1024 blocks).
// Sparsity-aware. chanmean reads f32 att (always correct).
// ============================================================================
__global__ void __launch_bounds__(256, 2) k4_gemm4_tail(
    float* __restrict__ outp, float* __restrict__ attsp,
    const float* __restrict__ att)
{
    const int b = blockIdx.x;
    const int t = threadIdx.x;
    if (b >= 128) {
        const int g = b - 128;
        const int rb = g >> 3;
        const int bm = rb * 128;
        const int bn = (g & 7) * 128;
        if (g_bflag[rb] == 0) {
            float4 z = make_float4(0.f, 0.f, 0.f, 0.f);
#pragma unroll
            for (int i = 0; i < 16; i++) {
                int u = t + i * 256;
                int r = u >> 5;
                int c4 = u & 31;
                ((float4*)&outp[(size_t)(bm + r) * SPATIAL + bn])[c4] = z;
            }
            return;
        }
        gemm16_tile<false, false>(SPATIAL, MDIM, g_atth, g_mnTh, outp, nullptr,
                                  nullptr, bm, bn);
        return;
    }
    const int n  = b >> 2;
    const int mg = b & 3;
    const int any = g_bflag[4 * n] | g_bflag[4 * n + 1] |
                    g_bflag[4 * n + 2] | g_bflag[4 * n + 3];
    float* dst0 = attsp + ((size_t)(n * MDIM + mg * 128)) * SPATIAL;
    if (any == 0) {
        float4 z = make_float4(0.f, 0.f, 0.f, 0.f);
        for (int m2 = 0; m2 < 128; m2++)
            ((float4*)(dst0 + (size_t)m2 * SPATIAL))[t] = z;
        return;
    }
    extern __shared__ float sf[];
    const int m  = t & 127;
    const int ch = t >> 7;
    const float* base = att + ((size_t)(n * 512 + ch * 256)) * MDIM + mg * 128 + m;
    float s = 0.0f;
#pragma unroll 4
    for (int c = 0; c < 256; c++) s += base[(size_t)c * MDIM];
    sf[t] = s;
    __syncthreads();
    if (t < 128) sf[256 + t] = (sf[t] + sf[t + 128]) * (1.0f / 512.0f);
    __syncthreads();
    for (int m2 = 0; m2 < 128; m2++) {
        const float v = sf[256 + m2];
        ((float4*)(dst0 + (size_t)m2 * SPATIAL))[t] = make_float4(v, v, v, v);
    }
}

// ============================================================================
extern "C" void kernel_launch(void* const* d_in, const int* in_sizes, int n_in,
                              void* d_out, int out_size) {
    (void)in_sizes; (void)n_in; (void)out_size;
    const float* x      = (const float*)d_in[0];
    const float* memory = (const float*)d_in[1];
    const float* w1     = (const float*)d_in[2];
    const float* b1     = (const float*)d_in[3];
    const float* w2     = (const float*)d_in[4];
    const float* b2     = (const float*)d_in[5];

    float* out = (float*)d_out;
    float* out_output  = out + OFF_OUTPUT;
    float* out_attsp   = out + OFF_ATTSP;
    float* out_inflat  = out + OFF_INFLAT;
    float* out_memnorm = out + OFF_MEMNORM;
    float* out_att     = out + OFF_ATT;

    cudaFuncSetAttribute((const void*)k1_mlp1_input,
                         cudaFuncAttributeMaxDynamicSharedMemorySize, GEMM_SMEM_BYTES);
    cudaFuncSetAttribute((const void*)k2_mlp2_input,
                         cudaFuncAttributeMaxDynamicSharedMemorySize, GEMM_SMEM_BYTES);
    cudaFuncSetAttribute((const void*)gemm3_stats_kernel,
                         cudaFuncAttributeMaxDynamicSharedMemorySize, HGEMM_SMEM_BYTES);
    cudaFuncSetAttribute((const void*)fb_logits_kernel,
                         cudaFuncAttributeMaxDynamicSharedMemorySize, HGEMM_SMEM_BYTES);
    cudaFuncSetAttribute((const void*)k4_gemm4_tail,
                         cudaFuncAttributeMaxDynamicSharedMemorySize, HGEMM_SMEM_BYTES);

    // L1: MLP layer 1 || input processing (rows 0..8191)
    k1_mlp1_input<<<148, 256, GEMM_SMEM_BYTES>>>(memory, w1, b1, x, out_inflat);
    // L2: MLP layer 2 || input processing (rows 8192..16383)
    k2_mlp2_input<<<148, 256, GEMM_SMEM_BYTES>>>(w2, b2, x, out_inflat);
    // L3: memory_norm (f32 + fp16 + fp16^T)
    rownorm_t_kernel<<<MDIM, 256>>>(out_memnorm);
    // L4: fp16 addressing GEMM -> per-row softmax stats (+ flag reset)
    gemm3_stats_kernel<<<512, 256, HGEMM_SMEM_BYTES>>>();
    // L5: merge stats -> survivor flags; zero f32 att for clear rows
    flagzero_kernel<<<R_ROWS / 8, 256>>>(out_att);
    // L6: exact fp16 logits for flagged blocks (no-op when none)
    fb_logits_kernel<<<512, 256, HGEMM_SMEM_BYTES>>>();
    // L7: exact softmax for flagged blocks (no-op when none)
    fb_softmax_kernel<<<R_ROWS / 8, 256>>>(out_att);
    // L8: output GEMM (sparsity-aware) + fused channel-mean/broadcast
    k4_gemm4_tail<<<1152, 256, HGEMM_SMEM_BYTES>>>(out_output, out_attsp, out_att);
}